// round 1
// baseline (speedup 1.0000x reference)
#include <cuda_runtime.h>
#include <cstddef>

#define D 1024
#define BATCH 16
#define SEQ 2048
#define NTOK (BATCH * SEQ)   // 32768

// ---------------- scratch (static __device__, no allocations) ----------------
__device__ float g_h[(size_t)NTOK * D];        // gathered embeddings      134 MB
__device__ float g_G[(size_t)NTOK * D];        // h @ (Wq Wk^T)            134 MB
__device__ float g_V[(size_t)NTOK * D];        // h @ Wv + bv              134 MB
__device__ float g_M[(size_t)D * D];           // Wq @ Wk^T                  4 MB
__device__ float g_r[D];                       // Wk @ bq
__device__ float g_t[NTOK];                    // (h . r)/32  (key-side bias term)
__device__ float g_scores[(size_t)BATCH * SEQ * SEQ];   // 268 MB
__device__ float g_w[NTOK];                    // attn column sums [B][S]

// ---------------- small kernels ----------------

__global__ void zero_w_kernel(float* w) {
    w[blockIdx.x * blockDim.x + threadIdx.x] = 0.0f;
}

// r[e] = sum_j wk[e][j] * bq[j]
__global__ void prep_r_kernel(const float* __restrict__ wk,
                              const float* __restrict__ bq,
                              float* __restrict__ r) {
    int e = blockIdx.x * blockDim.x + threadIdx.x;
    if (e < D) {
        float s = 0.0f;
        const float* row = wk + (size_t)e * D;
        for (int j = 0; j < D; j++) s = fmaf(row[j], bq[j], s);
        r[e] = s;
    }
}

// h[n,:] = (X[n]==0) ? 0 : emb[X[n],:];   t[n] = (h[n,:] . r) / 32
__global__ __launch_bounds__(256) void gather_kernel(const int* __restrict__ X,
                                                     const float* __restrict__ emb,
                                                     const float* __restrict__ r,
                                                     float* __restrict__ h,
                                                     float* __restrict__ t) {
    int n = blockIdx.x;
    int tid = threadIdx.x;   // 256 threads, one float4 each
    int tok = X[n];
    float4 hv = make_float4(0.f, 0.f, 0.f, 0.f);
    if (tok != 0) hv = ((const float4*)(emb + (size_t)tok * D))[tid];
    ((float4*)(h + (size_t)n * D))[tid] = hv;

    float4 rv = ((const float4*)r)[tid];
    float s = hv.x * rv.x + hv.y * rv.y + hv.z * rv.z + hv.w * rv.w;

    // reduce 256 -> 1
    #pragma unroll
    for (int o = 16; o > 0; o >>= 1) s += __shfl_xor_sync(0xffffffffu, s, o);
    __shared__ float sh[8];
    int lane = tid & 31, warp = tid >> 5;
    if (lane == 0) sh[warp] = s;
    __syncthreads();
    if (tid == 0) {
        float acc = sh[0];
        #pragma unroll
        for (int i = 1; i < 8; i++) acc += sh[i];
        t[n] = acc * 0.03125f;   // 1/sqrt(1024)
    }
}

// ---------------- 128x128x16 fp32 tiled GEMMs (256 thr, 8x8 microtile) ----------------

// C[M,N] = A[M,K] @ B[K,N] (+ bias[col]) — all row-major, dims multiples of 128/16.
__global__ __launch_bounds__(256) void gemm_nn_kernel(const float* __restrict__ A,
                                                      const float* __restrict__ B,
                                                      const float* __restrict__ bias,
                                                      float* __restrict__ C,
                                                      int M, int N, int K) {
    __shared__ float As[16][128];
    __shared__ float Bs[16][128];
    int tid = threadIdx.x;
    int tx = tid & 15, ty = tid >> 4;
    const float* Ab = A + (size_t)blockIdx.y * 128 * K;
    const float* Bb = B + (size_t)blockIdx.x * 128;
    float acc[8][8];
    #pragma unroll
    for (int i = 0; i < 8; i++)
        #pragma unroll
        for (int j = 0; j < 8; j++) acc[i][j] = 0.0f;

    for (int k0 = 0; k0 < K; k0 += 16) {
        #pragma unroll
        for (int i = 0; i < 2; i++) {
            int idx = tid + (i << 8);             // 0..511
            int ar = idx >> 2, ac = (idx & 3) << 2;   // A: 128 rows x 16 cols
            float4 av = *(const float4*)(Ab + (size_t)ar * K + k0 + ac);
            As[ac + 0][ar] = av.x; As[ac + 1][ar] = av.y;
            As[ac + 2][ar] = av.z; As[ac + 3][ar] = av.w;
            int br = idx >> 5, bc = (idx & 31) << 2;  // B: 16 rows x 128 cols
            float4 bv = *(const float4*)(Bb + (size_t)(k0 + br) * N + bc);
            *(float4*)&Bs[br][bc] = bv;
        }
        __syncthreads();
        #pragma unroll
        for (int k = 0; k < 16; k++) {
            float a[8], b[8];
            *(float4*)&a[0] = *(const float4*)&As[k][ty * 8];
            *(float4*)&a[4] = *(const float4*)&As[k][ty * 8 + 4];
            *(float4*)&b[0] = *(const float4*)&Bs[k][tx * 8];
            *(float4*)&b[4] = *(const float4*)&Bs[k][tx * 8 + 4];
            #pragma unroll
            for (int i = 0; i < 8; i++)
                #pragma unroll
                for (int j = 0; j < 8; j++) acc[i][j] = fmaf(a[i], b[j], acc[i][j]);
        }
        __syncthreads();
    }

    float* Cb = C + (size_t)blockIdx.y * 128 * N + (size_t)blockIdx.x * 128;
    #pragma unroll
    for (int i = 0; i < 8; i++) {
        int row = ty * 8 + i;
        #pragma unroll
        for (int j = 0; j < 8; j += 4) {
            int col = tx * 8 + j;
            float4 v;
            v.x = acc[i][j];     v.y = acc[i][j + 1];
            v.z = acc[i][j + 2]; v.w = acc[i][j + 3];
            if (bias) {
                int gc = blockIdx.x * 128 + col;
                v.x += bias[gc]; v.y += bias[gc + 1];
                v.z += bias[gc + 2]; v.w += bias[gc + 3];
            }
            *(float4*)(Cb + (size_t)row * N + col) = v;
        }
    }
}

// C[M,N] = scale * (A[M,K] @ Bt[N,K]^T) + addvec[col]; batched via blockIdx.z strides.
__global__ __launch_bounds__(256) void gemm_nt_kernel(const float* __restrict__ A,
                                                      const float* __restrict__ Bt,
                                                      float* __restrict__ C,
                                                      int M, int N, int K,
                                                      float scale,
                                                      const float* __restrict__ addvec,
                                                      size_t aStride, size_t bStride,
                                                      size_t cStride, int vStride) {
    int z = blockIdx.z;
    const float* Ab = A + (size_t)z * aStride + (size_t)blockIdx.y * 128 * K;
    const float* Bb = Bt + (size_t)z * bStride + (size_t)blockIdx.x * 128 * K;
    __shared__ float As[16][128];
    __shared__ float Bs[16][128];
    int tid = threadIdx.x;
    int tx = tid & 15, ty = tid >> 4;
    float acc[8][8];
    #pragma unroll
    for (int i = 0; i < 8; i++)
        #pragma unroll
        for (int j = 0; j < 8; j++) acc[i][j] = 0.0f;

    for (int k0 = 0; k0 < K; k0 += 16) {
        #pragma unroll
        for (int i = 0; i < 2; i++) {
            int idx = tid + (i << 8);
            int r8 = idx >> 2, c4 = (idx & 3) << 2;   // 128 rows x 16 cols (both A and Bt)
            float4 av = *(const float4*)(Ab + (size_t)r8 * K + k0 + c4);
            As[c4 + 0][r8] = av.x; As[c4 + 1][r8] = av.y;
            As[c4 + 2][r8] = av.z; As[c4 + 3][r8] = av.w;
            float4 bv = *(const float4*)(Bb + (size_t)r8 * K + k0 + c4);
            Bs[c4 + 0][r8] = bv.x; Bs[c4 + 1][r8] = bv.y;
            Bs[c4 + 2][r8] = bv.z; Bs[c4 + 3][r8] = bv.w;
        }
        __syncthreads();
        #pragma unroll
        for (int k = 0; k < 16; k++) {
            float a[8], b[8];
            *(float4*)&a[0] = *(const float4*)&As[k][ty * 8];
            *(float4*)&a[4] = *(const float4*)&As[k][ty * 8 + 4];
            *(float4*)&b[0] = *(const float4*)&Bs[k][tx * 8];
            *(float4*)&b[4] = *(const float4*)&Bs[k][tx * 8 + 4];
            #pragma unroll
            for (int i = 0; i < 8; i++)
                #pragma unroll
                for (int j = 0; j < 8; j++) acc[i][j] = fmaf(a[i], b[j], acc[i][j]);
        }
        __syncthreads();
    }

    float* Cb = C + (size_t)z * cStride + (size_t)blockIdx.y * 128 * N + (size_t)blockIdx.x * 128;
    const float* av = addvec ? (addvec + (size_t)z * vStride + blockIdx.x * 128) : nullptr;
    #pragma unroll
    for (int i = 0; i < 8; i++) {
        int row = ty * 8 + i;
        #pragma unroll
        for (int j = 0; j < 8; j += 4) {
            int col = tx * 8 + j;
            float4 v;
            v.x = acc[i][j] * scale;     v.y = acc[i][j + 1] * scale;
            v.z = acc[i][j + 2] * scale; v.w = acc[i][j + 3] * scale;
            if (av) {
                v.x += av[col]; v.y += av[col + 1];
                v.z += av[col + 2]; v.w += av[col + 3];
            }
            *(float4*)(Cb + (size_t)row * N + col) = v;
        }
    }
}

// ---------------- softmax + column-sum: w[b,k] = sum_q softmax(scores[b,q,:])[k] ----------------
__global__ __launch_bounds__(256) void softmax_colsum_kernel(const float* __restrict__ scores,
                                                             float* __restrict__ w) {
    int b = blockIdx.y;
    int row0 = blockIdx.x * 64;     // 64 query rows per block
    int tid = threadIdx.x;
    int lane = tid & 31, warp = tid >> 5;
    const float* Sb = scores + (size_t)b * SEQ * SEQ;
    __shared__ float sh[8];
    float colacc[8];
    #pragma unroll
    for (int i = 0; i < 8; i++) colacc[i] = 0.0f;

    for (int r = 0; r < 64; r++) {
        const float* row = Sb + (size_t)(row0 + r) * SEQ;
        float v[8];
        float m = -3.4e38f;
        #pragma unroll
        for (int i = 0; i < 8; i++) { v[i] = row[tid + (i << 8)]; m = fmaxf(m, v[i]); }
        #pragma unroll
        for (int o = 16; o > 0; o >>= 1) m = fmaxf(m, __shfl_xor_sync(0xffffffffu, m, o));
        if (lane == 0) sh[warp] = m;
        __syncthreads();
        m = sh[0];
        #pragma unroll
        for (int i = 1; i < 8; i++) m = fmaxf(m, sh[i]);
        __syncthreads();

        float e[8], s = 0.0f;
        #pragma unroll
        for (int i = 0; i < 8; i++) { e[i] = __expf(v[i] - m); s += e[i]; }
        #pragma unroll
        for (int o = 16; o > 0; o >>= 1) s += __shfl_xor_sync(0xffffffffu, s, o);
        if (lane == 0) sh[warp] = s;
        __syncthreads();
        s = sh[0];
        #pragma unroll
        for (int i = 1; i < 8; i++) s += sh[i];
        float inv = 1.0f / s;
        __syncthreads();
        #pragma unroll
        for (int i = 0; i < 8; i++) colacc[i] = fmaf(e[i], inv, colacc[i]);
    }
    #pragma unroll
    for (int i = 0; i < 8; i++) atomicAdd(&w[b * SEQ + tid + (i << 8)], colacc[i]);
}

// ---------------- context[b,d] = (1/S) * sum_k w[b,k] * V[b,k,d] ----------------
__global__ __launch_bounds__(256) void context_kernel(const float* __restrict__ w,
                                                      const float* __restrict__ V,
                                                      float* __restrict__ out) {
    int b = blockIdx.y;
    int d = blockIdx.x * 256 + threadIdx.x;
    __shared__ float ws[SEQ];
    for (int i = threadIdx.x; i < SEQ; i += 256) ws[i] = w[b * SEQ + i];
    __syncthreads();
    const float* Vb = V + (size_t)b * SEQ * D + d;
    float acc0 = 0.f, acc1 = 0.f, acc2 = 0.f, acc3 = 0.f;
    #pragma unroll 4
    for (int k = 0; k < SEQ; k += 4) {
        acc0 = fmaf(ws[k + 0], Vb[(size_t)(k + 0) * D], acc0);
        acc1 = fmaf(ws[k + 1], Vb[(size_t)(k + 1) * D], acc1);
        acc2 = fmaf(ws[k + 2], Vb[(size_t)(k + 2) * D], acc2);
        acc3 = fmaf(ws[k + 3], Vb[(size_t)(k + 3) * D], acc3);
    }
    out[b * D + d] = (acc0 + acc1 + acc2 + acc3) * (1.0f / SEQ);
}

// ---------------- launch ----------------
extern "C" void kernel_launch(void* const* d_in, const int* in_sizes, int n_in,
                              void* d_out, int out_size) {
    const int*   X   = (const int*)d_in[0];
    const float* emb = (const float*)d_in[1];
    const float* wq  = (const float*)d_in[2];
    const float* bq  = (const float*)d_in[3];
    const float* wk  = (const float*)d_in[4];
    // const float* bk = (const float*)d_in[5];   // cancels in softmax (row-constant)
    const float* wv  = (const float*)d_in[6];
    const float* bv  = (const float*)d_in[7];
    float* out = (float*)d_out;

    void *p;
    cudaGetSymbolAddress(&p, g_h);      float* h      = (float*)p;
    cudaGetSymbolAddress(&p, g_G);      float* G      = (float*)p;
    cudaGetSymbolAddress(&p, g_V);      float* V      = (float*)p;
    cudaGetSymbolAddress(&p, g_M);      float* Mm     = (float*)p;
    cudaGetSymbolAddress(&p, g_r);      float* r      = (float*)p;
    cudaGetSymbolAddress(&p, g_t);      float* t      = (float*)p;
    cudaGetSymbolAddress(&p, g_scores); float* scores = (float*)p;
    cudaGetSymbolAddress(&p, g_w);      float* w      = (float*)p;

    dim3 blk(256);
    zero_w_kernel<<<NTOK / 256, blk>>>(w);
    prep_r_kernel<<<D / 256, blk>>>(wk, bq, r);
    // M = Wq @ Wk^T  (1024^3 NT)
    gemm_nt_kernel<<<dim3(8, 8, 1), blk>>>(wq, wk, Mm, D, D, D, 1.0f, nullptr, 0, 0, 0, 0);
    // gather h + key-side bias term t
    gather_kernel<<<NTOK, blk>>>(X, emb, r, h, t);
    // G = h @ M
    gemm_nn_kernel<<<dim3(D / 128, NTOK / 128, 1), blk>>>(h, Mm, nullptr, G, NTOK, D, D);
    // V = h @ Wv + bv
    gemm_nn_kernel<<<dim3(D / 128, NTOK / 128, 1), blk>>>(h, wv, bv, V, NTOK, D, D);
    // scores[b] = (G_b @ h_b^T)/32 + t_b[col]   (batched NT)
    gemm_nt_kernel<<<dim3(SEQ / 128, SEQ / 128, BATCH), blk>>>(
        G, h, scores, SEQ, SEQ, D, 0.03125f, t,
        (size_t)SEQ * D, (size_t)SEQ * D, (size_t)SEQ * SEQ, SEQ);
    // row softmax + column sums
    softmax_colsum_kernel<<<dim3(SEQ / 64, BATCH), blk>>>(scores, w);
    // context = (w @ V) / S
    context_kernel<<<dim3(D / 256, BATCH), blk>>>(w, V, out);
}

// round 2
// speedup vs baseline: 1.0011x; 1.0011x over previous
#include <cuda_runtime.h>
#include <cstddef>

#define D 1024
#define BATCH 16
#define SEQ 2048
#define NTOK (BATCH * SEQ)   // 32768

// ---------------- scratch (static __device__, no allocations) ----------------
__device__ float g_h[(size_t)NTOK * D];        // gathered embeddings      134 MB
__device__ float g_G[(size_t)NTOK * D];        // h @ (Wq Wk^T)            134 MB
__device__ float g_V[(size_t)NTOK * D];        // h @ Wv + bv              134 MB
__device__ float g_M[(size_t)D * D];           // Wq @ Wk^T                  4 MB
__device__ float g_r[D];                       // Wk @ bq
__device__ float g_t[NTOK];                    // (h . r)/32  (key-side bias term)
__device__ float g_scores[(size_t)BATCH * SEQ * SEQ];   // 268 MB
__device__ float g_w[NTOK];                    // attn column sums [B][S]

// ---------------- small kernels ----------------

__global__ void zero_w_kernel(float* w) {
    w[blockIdx.x * blockDim.x + threadIdx.x] = 0.0f;
}

// r[e] = sum_j wk[e][j] * bq[j]
__global__ void prep_r_kernel(const float* __restrict__ wk,
                              const float* __restrict__ bq,
                              float* __restrict__ r) {
    int e = blockIdx.x * blockDim.x + threadIdx.x;
    if (e < D) {
        float s = 0.0f;
        const float* row = wk + (size_t)e * D;
        for (int j = 0; j < D; j++) s = fmaf(row[j], bq[j], s);
        r[e] = s;
    }
}

// h[n,:] = (X[n]==0) ? 0 : emb[X[n],:];   t[n] = (h[n,:] . r) / 32
__global__ __launch_bounds__(256) void gather_kernel(const int* __restrict__ X,
                                                     const float* __restrict__ emb,
                                                     const float* __restrict__ r,
                                                     float* __restrict__ h,
                                                     float* __restrict__ t) {
    int n = blockIdx.x;
    int tid = threadIdx.x;   // 256 threads, one float4 each
    int tok = X[n];
    float4 hv = make_float4(0.f, 0.f, 0.f, 0.f);
    if (tok != 0) hv = ((const float4*)(emb + (size_t)tok * D))[tid];
    ((float4*)(h + (size_t)n * D))[tid] = hv;

    float4 rv = ((const float4*)r)[tid];
    float s = hv.x * rv.x + hv.y * rv.y + hv.z * rv.z + hv.w * rv.w;

    // reduce 256 -> 1
    #pragma unroll
    for (int o = 16; o > 0; o >>= 1) s += __shfl_xor_sync(0xffffffffu, s, o);
    __shared__ float sh[8];
    int lane = tid & 31, warp = tid >> 5;
    if (lane == 0) sh[warp] = s;
    __syncthreads();
    if (tid == 0) {
        float acc = sh[0];
        #pragma unroll
        for (int i = 1; i < 8; i++) acc += sh[i];
        t[n] = acc * 0.03125f;   // 1/sqrt(1024)
    }
}

// ---------------- 128x128x16 fp32 tiled GEMMs (256 thr, 8x8 microtile) ----------------

// C[M,N] = A[M,K] @ B[K,N] (+ bias[col]) — all row-major, dims multiples of 128/16.
__global__ __launch_bounds__(256) void gemm_nn_kernel(const float* __restrict__ A,
                                                      const float* __restrict__ B,
                                                      const float* __restrict__ bias,
                                                      float* __restrict__ C,
                                                      int M, int N, int K) {
    __shared__ float As[16][128];
    __shared__ float Bs[16][128];
    int tid = threadIdx.x;
    int tx = tid & 15, ty = tid >> 4;
    const float* Ab = A + (size_t)blockIdx.y * 128 * K;
    const float* Bb = B + (size_t)blockIdx.x * 128;
    float acc[8][8];
    #pragma unroll
    for (int i = 0; i < 8; i++)
        #pragma unroll
        for (int j = 0; j < 8; j++) acc[i][j] = 0.0f;

    for (int k0 = 0; k0 < K; k0 += 16) {
        #pragma unroll
        for (int i = 0; i < 2; i++) {
            int idx = tid + (i << 8);             // 0..511
            int ar = idx >> 2, ac = (idx & 3) << 2;   // A: 128 rows x 16 cols
            float4 av = *(const float4*)(Ab + (size_t)ar * K + k0 + ac);
            As[ac + 0][ar] = av.x; As[ac + 1][ar] = av.y;
            As[ac + 2][ar] = av.z; As[ac + 3][ar] = av.w;
            int br = idx >> 5, bc = (idx & 31) << 2;  // B: 16 rows x 128 cols
            float4 bv = *(const float4*)(Bb + (size_t)(k0 + br) * N + bc);
            *(float4*)&Bs[br][bc] = bv;
        }
        __syncthreads();
        #pragma unroll
        for (int k = 0; k < 16; k++) {
            float a[8], b[8];
            *(float4*)&a[0] = *(const float4*)&As[k][ty * 8];
            *(float4*)&a[4] = *(const float4*)&As[k][ty * 8 + 4];
            *(float4*)&b[0] = *(const float4*)&Bs[k][tx * 8];
            *(float4*)&b[4] = *(const float4*)&Bs[k][tx * 8 + 4];
            #pragma unroll
            for (int i = 0; i < 8; i++)
                #pragma unroll
                for (int j = 0; j < 8; j++) acc[i][j] = fmaf(a[i], b[j], acc[i][j]);
        }
        __syncthreads();
    }

    float* Cb = C + (size_t)blockIdx.y * 128 * N + (size_t)blockIdx.x * 128;
    #pragma unroll
    for (int i = 0; i < 8; i++) {
        int row = ty * 8 + i;
        #pragma unroll
        for (int j = 0; j < 8; j += 4) {
            int col = tx * 8 + j;
            float4 v;
            v.x = acc[i][j];     v.y = acc[i][j + 1];
            v.z = acc[i][j + 2]; v.w = acc[i][j + 3];
            if (bias) {
                int gc = blockIdx.x * 128 + col;
                v.x += bias[gc]; v.y += bias[gc + 1];
                v.z += bias[gc + 2]; v.w += bias[gc + 3];
            }
            *(float4*)(Cb + (size_t)row * N + col) = v;
        }
    }
}

// C[M,N] = scale * (A[M,K] @ Bt[N,K]^T) + addvec[col]; batched via blockIdx.z strides.
__global__ __launch_bounds__(256) void gemm_nt_kernel(const float* __restrict__ A,
                                                      const float* __restrict__ Bt,
                                                      float* __restrict__ C,
                                                      int M, int N, int K,
                                                      float scale,
                                                      const float* __restrict__ addvec,
                                                      size_t aStride, size_t bStride,
                                                      size_t cStride, int vStride) {
    int z = blockIdx.z;
    const float* Ab = A + (size_t)z * aStride + (size_t)blockIdx.y * 128 * K;
    const float* Bb = Bt + (size_t)z * bStride + (size_t)blockIdx.x * 128 * K;
    __shared__ float As[16][128];
    __shared__ float Bs[16][128];
    int tid = threadIdx.x;
    int tx = tid & 15, ty = tid >> 4;
    float acc[8][8];
    #pragma unroll
    for (int i = 0; i < 8; i++)
        #pragma unroll
        for (int j = 0; j < 8; j++) acc[i][j] = 0.0f;

    for (int k0 = 0; k0 < K; k0 += 16) {
        #pragma unroll
        for (int i = 0; i < 2; i++) {
            int idx = tid + (i << 8);
            int r8 = idx >> 2, c4 = (idx & 3) << 2;   // 128 rows x 16 cols (both A and Bt)
            float4 av = *(const float4*)(Ab + (size_t)r8 * K + k0 + c4);
            As[c4 + 0][r8] = av.x; As[c4 + 1][r8] = av.y;
            As[c4 + 2][r8] = av.z; As[c4 + 3][r8] = av.w;
            float4 bv = *(const float4*)(Bb + (size_t)r8 * K + k0 + c4);
            Bs[c4 + 0][r8] = bv.x; Bs[c4 + 1][r8] = bv.y;
            Bs[c4 + 2][r8] = bv.z; Bs[c4 + 3][r8] = bv.w;
        }
        __syncthreads();
        #pragma unroll
        for (int k = 0; k < 16; k++) {
            float a[8], b[8];
            *(float4*)&a[0] = *(const float4*)&As[k][ty * 8];
            *(float4*)&a[4] = *(const float4*)&As[k][ty * 8 + 4];
            *(float4*)&b[0] = *(const float4*)&Bs[k][tx * 8];
            *(float4*)&b[4] = *(const float4*)&Bs[k][tx * 8 + 4];
            #pragma unroll
            for (int i = 0; i < 8; i++)
                #pragma unroll
                for (int j = 0; j < 8; j++) acc[i][j] = fmaf(a[i], b[j], acc[i][j]);
        }
        __syncthreads();
    }

    float* Cb = C + (size_t)z * cStride + (size_t)blockIdx.y * 128 * N + (size_t)blockIdx.x * 128;
    const float* av = addvec ? (addvec + (size_t)z * vStride + blockIdx.x * 128) : nullptr;
    #pragma unroll
    for (int i = 0; i < 8; i++) {
        int row = ty * 8 + i;
        #pragma unroll
        for (int j = 0; j < 8; j += 4) {
            int col = tx * 8 + j;
            float4 v;
            v.x = acc[i][j] * scale;     v.y = acc[i][j + 1] * scale;
            v.z = acc[i][j + 2] * scale; v.w = acc[i][j + 3] * scale;
            if (av) {
                v.x += av[col]; v.y += av[col + 1];
                v.z += av[col + 2]; v.w += av[col + 3];
            }
            *(float4*)(Cb + (size_t)row * N + col) = v;
        }
    }
}

// ---------------- softmax + column-sum: w[b,k] = sum_q softmax(scores[b,q,:])[k] ----------------
__global__ __launch_bounds__(256) void softmax_colsum_kernel(const float* __restrict__ scores,
                                                             float* __restrict__ w) {
    int b = blockIdx.y;
    int row0 = blockIdx.x * 64;     // 64 query rows per block
    int tid = threadIdx.x;
    int lane = tid & 31, warp = tid >> 5;
    const float* Sb = scores + (size_t)b * SEQ * SEQ;
    __shared__ float sh[8];
    float colacc[8];
    #pragma unroll
    for (int i = 0; i < 8; i++) colacc[i] = 0.0f;

    for (int r = 0; r < 64; r++) {
        const float* row = Sb + (size_t)(row0 + r) * SEQ;
        float v[8];
        float m = -3.4e38f;
        #pragma unroll
        for (int i = 0; i < 8; i++) { v[i] = row[tid + (i << 8)]; m = fmaxf(m, v[i]); }
        #pragma unroll
        for (int o = 16; o > 0; o >>= 1) m = fmaxf(m, __shfl_xor_sync(0xffffffffu, m, o));
        if (lane == 0) sh[warp] = m;
        __syncthreads();
        m = sh[0];
        #pragma unroll
        for (int i = 1; i < 8; i++) m = fmaxf(m, sh[i]);
        __syncthreads();

        float e[8], s = 0.0f;
        #pragma unroll
        for (int i = 0; i < 8; i++) { e[i] = __expf(v[i] - m); s += e[i]; }
        #pragma unroll
        for (int o = 16; o > 0; o >>= 1) s += __shfl_xor_sync(0xffffffffu, s, o);
        if (lane == 0) sh[warp] = s;
        __syncthreads();
        s = sh[0];
        #pragma unroll
        for (int i = 1; i < 8; i++) s += sh[i];
        float inv = 1.0f / s;
        __syncthreads();
        #pragma unroll
        for (int i = 0; i < 8; i++) colacc[i] = fmaf(e[i], inv, colacc[i]);
    }
    #pragma unroll
    for (int i = 0; i < 8; i++) atomicAdd(&w[b * SEQ + tid + (i << 8)], colacc[i]);
}

// ---------------- context[b,d] = (1/S) * sum_k w[b,k] * V[b,k,d] ----------------
__global__ __launch_bounds__(256) void context_kernel(const float* __restrict__ w,
                                                      const float* __restrict__ V,
                                                      float* __restrict__ out) {
    int b = blockIdx.y;
    int d = blockIdx.x * 256 + threadIdx.x;
    __shared__ float ws[SEQ];
    for (int i = threadIdx.x; i < SEQ; i += 256) ws[i] = w[b * SEQ + i];
    __syncthreads();
    const float* Vb = V + (size_t)b * SEQ * D + d;
    float acc0 = 0.f, acc1 = 0.f, acc2 = 0.f, acc3 = 0.f;
    #pragma unroll 4
    for (int k = 0; k < SEQ; k += 4) {
        acc0 = fmaf(ws[k + 0], Vb[(size_t)(k + 0) * D], acc0);
        acc1 = fmaf(ws[k + 1], Vb[(size_t)(k + 1) * D], acc1);
        acc2 = fmaf(ws[k + 2], Vb[(size_t)(k + 2) * D], acc2);
        acc3 = fmaf(ws[k + 3], Vb[(size_t)(k + 3) * D], acc3);
    }
    out[b * D + d] = (acc0 + acc1 + acc2 + acc3) * (1.0f / SEQ);
}

// ---------------- launch ----------------
extern "C" void kernel_launch(void* const* d_in, const int* in_sizes, int n_in,
                              void* d_out, int out_size) {
    const int*   X   = (const int*)d_in[0];
    const float* emb = (const float*)d_in[1];
    const float* wq  = (const float*)d_in[2];
    const float* bq  = (const float*)d_in[3];
    const float* wk  = (const float*)d_in[4];
    // const float* bk = (const float*)d_in[5];   // cancels in softmax (row-constant)
    const float* wv  = (const float*)d_in[6];
    const float* bv  = (const float*)d_in[7];
    float* out = (float*)d_out;

    void *p;
    cudaGetSymbolAddress(&p, g_h);      float* h      = (float*)p;
    cudaGetSymbolAddress(&p, g_G);      float* G      = (float*)p;
    cudaGetSymbolAddress(&p, g_V);      float* V      = (float*)p;
    cudaGetSymbolAddress(&p, g_M);      float* Mm     = (float*)p;
    cudaGetSymbolAddress(&p, g_r);      float* r      = (float*)p;
    cudaGetSymbolAddress(&p, g_t);      float* t      = (float*)p;
    cudaGetSymbolAddress(&p, g_scores); float* scores = (float*)p;
    cudaGetSymbolAddress(&p, g_w);      float* w      = (float*)p;

    dim3 blk(256);
    zero_w_kernel<<<NTOK / 256, blk>>>(w);
    prep_r_kernel<<<D / 256, blk>>>(wk, bq, r);
    // M = Wq @ Wk^T  (1024^3 NT)
    gemm_nt_kernel<<<dim3(8, 8, 1), blk>>>(wq, wk, Mm, D, D, D, 1.0f, nullptr, 0, 0, 0, 0);
    // gather h + key-side bias term t
    gather_kernel<<<NTOK, blk>>>(X, emb, r, h, t);
    // G = h @ M
    gemm_nn_kernel<<<dim3(D / 128, NTOK / 128, 1), blk>>>(h, Mm, nullptr, G, NTOK, D, D);
    // V = h @ Wv + bv
    gemm_nn_kernel<<<dim3(D / 128, NTOK / 128, 1), blk>>>(h, wv, bv, V, NTOK, D, D);
    // scores[b] = (G_b @ h_b^T)/32 + t_b[col]   (batched NT)
    gemm_nt_kernel<<<dim3(SEQ / 128, SEQ / 128, BATCH), blk>>>(
        G, h, scores, SEQ, SEQ, D, 0.03125f, t,
        (size_t)SEQ * D, (size_t)SEQ * D, (size_t)SEQ * SEQ, SEQ);
    // row softmax + column sums
    softmax_colsum_kernel<<<dim3(SEQ / 64, BATCH), blk>>>(scores, w);
    // context = (w @ V) / S
    context_kernel<<<dim3(D / 256, BATCH), blk>>>(w, V, out);
}